// round 9
// baseline (speedup 1.0000x reference)
#include <cuda_runtime.h>
#include <cuda_bf16.h>
#include <math_constants.h>
#include <cstdint>

// Problem constants
#define B_   1024
#define NTOK 68
#define C_   768
#define H_   12
#define HD   64
#define M_   (B_ * NTOK)        // 69632
#define K3C  (3 * C_)           // 2304

// Scratch (__device__ globals; allocation-free rule)
__device__ float         g_qkv[(size_t)M_ * K3C];   // QKV output fp32
__device__ __nv_bfloat16 g_xhi[(size_t)M_ * C_];    // x+pe split
__device__ __nv_bfloat16 g_xlo[(size_t)M_ * C_];
__device__ __nv_bfloat16 g_whi[(size_t)K3C * C_];   // w_qkv split
__device__ __nv_bfloat16 g_wlo[(size_t)K3C * C_];
__device__ __nv_bfloat16 g_phi[(size_t)C_ * C_];    // w_proj split
__device__ __nv_bfloat16 g_plo[(size_t)C_ * C_];
__device__ __nv_bfloat16 g_ahi[(size_t)M_ * C_];    // attention out split
__device__ __nv_bfloat16 g_alo[(size_t)M_ * C_];

// ---------------------------------------------------------------------------
// helpers
// ---------------------------------------------------------------------------
static __device__ __forceinline__ uint32_t smem_u32(const void* p) {
    uint32_t a;
    asm("{ .reg .u64 t; cvta.to.shared.u64 t, %1; cvt.u32.u64 %0, t; }"
        : "=r"(a) : "l"(p));
    return a;
}

static __device__ __forceinline__ void split2(float v, __nv_bfloat16& h,
                                              __nv_bfloat16& l) {
    h = __float2bfloat16_rn(v);
    l = __float2bfloat16_rn(v - __bfloat162float(h));
}

#define CP16(dst, src) \
    asm volatile("cp.async.cg.shared.global [%0], [%1], 16;" \
                 :: "r"(dst), "l"(src))
#define CP_COMMIT() asm volatile("cp.async.commit_group;" ::: "memory")
#define CP_WAIT2()  asm volatile("cp.async.wait_group 2;"  ::: "memory")

#define LDSM_X4(r, addr) \
    asm volatile("ldmatrix.sync.aligned.m8n8.x4.shared.b16 {%0,%1,%2,%3}, [%4];" \
                 : "=r"((r)[0]), "=r"((r)[1]), "=r"((r)[2]), "=r"((r)[3]) \
                 : "r"(addr))

#define MMA_BF16(d, a, b0, b1) \
    asm volatile("mma.sync.aligned.m16n8k16.row.col.f32.bf16.bf16.f32 " \
                 "{%0,%1,%2,%3}, {%4,%5,%6,%7}, {%8,%9}, {%0,%1,%2,%3};" \
                 : "+f"((d)[0]), "+f"((d)[1]), "+f"((d)[2]), "+f"((d)[3]) \
                 : "r"((a)[0]), "r"((a)[1]), "r"((a)[2]), "r"((a)[3]), \
                   "r"(b0), "r"(b1))

// smem tile: 128 rows x 32 bytes (16 bf16/row = one K-chunk of 16),
// 1-bit XOR swizzle -> conflict-free ldmatrix and cp.async stores.
// 4 stages x 4 tiles (Ahi, Alo, Bhi, Blo) x 4KB = 64KB -> 2 CTAs/SM.
static __device__ __forceinline__ uint32_t sw_off(int row, int c) {
    return (uint32_t)(row * 32 + (((c ^ (row >> 2)) & 1) << 4));
}
#define TILE_ST(s, w) ((s) * 16384 + (w) * 4096)
#define GEMM_SMEM 65536

// ---------------------------------------------------------------------------
// split kernels (fp32 -> bf16 hi/lo pair)
// ---------------------------------------------------------------------------
__global__ void split_x_pe_kernel(const float* __restrict__ x,
                                  const float* __restrict__ pe,
                                  __nv_bfloat16* __restrict__ hi,
                                  __nv_bfloat16* __restrict__ lo)
{
    const size_t i4 = (size_t)blockIdx.x * blockDim.x + threadIdx.x;
    const size_t e  = i4 * 4;
    if (e >= (size_t)M_ * C_) return;
    const int row = (int)(e / C_);
    const int col = (int)(e % C_);
    const int tok = row % NTOK;

    float4 v = *reinterpret_cast<const float4*>(x + e);
    if (tok >= 4) {
        const float4 p = *reinterpret_cast<const float4*>(
            pe + (size_t)(tok + 28) * C_ + col);
        v.x += p.x; v.y += p.y; v.z += p.z; v.w += p.w;
    }
    __nv_bfloat16 h0, l0, h1, l1, h2, l2, h3, l3;
    split2(v.x, h0, l0); split2(v.y, h1, l1);
    split2(v.z, h2, l2); split2(v.w, h3, l3);
    __nv_bfloat162* hp = reinterpret_cast<__nv_bfloat162*>(hi + e);
    __nv_bfloat162* lp = reinterpret_cast<__nv_bfloat162*>(lo + e);
    hp[0] = __nv_bfloat162(h0, h1); hp[1] = __nv_bfloat162(h2, h3);
    lp[0] = __nv_bfloat162(l0, l1); lp[1] = __nv_bfloat162(l2, l3);
}

__global__ void split_w_kernel(const float* __restrict__ w,
                               __nv_bfloat16* __restrict__ hi,
                               __nv_bfloat16* __restrict__ lo,
                               size_t n_elem)
{
    const size_t i4 = (size_t)blockIdx.x * blockDim.x + threadIdx.x;
    const size_t e  = i4 * 4;
    if (e >= n_elem) return;
    const float4 v = *reinterpret_cast<const float4*>(w + e);
    __nv_bfloat16 h0, l0, h1, l1, h2, l2, h3, l3;
    split2(v.x, h0, l0); split2(v.y, h1, l1);
    split2(v.z, h2, l2); split2(v.w, h3, l3);
    __nv_bfloat162* hp = reinterpret_cast<__nv_bfloat162*>(hi + e);
    __nv_bfloat162* lp = reinterpret_cast<__nv_bfloat162*>(lo + e);
    hp[0] = __nv_bfloat162(h0, h1); hp[1] = __nv_bfloat162(h2, h3);
    lp[0] = __nv_bfloat162(l0, l1); lp[1] = __nv_bfloat162(l2, l3);
}

// ---------------------------------------------------------------------------
// GEMM: C[m][n] = sum_k (Ahi+Alo)[m][k] * (Bhi+Blo)[n][k] + bias[n]
// D = Ahi*Bhi + Ahi*Blo + Alo*Bhi  (bf16 mma.sync, fp32 accum).
// CTA 128x128, 256 threads / 8 warps (2m x 4n), warp tile 64x32,
// K-chunk 16, 4-stage cp.async ring (64KB smem -> 2 CTAs/SM),
// term-major MMA schedule.
// ---------------------------------------------------------------------------
__global__ __launch_bounds__(256, 2)
void gemm_bf16x3_kernel(const __nv_bfloat16* __restrict__ Ahi,
                        const __nv_bfloat16* __restrict__ Alo,
                        const __nv_bfloat16* __restrict__ Bhi,
                        const __nv_bfloat16* __restrict__ Blo,
                        const float* __restrict__ bias,
                        float* __restrict__ Cout,
                        int N, int K)
{
    extern __shared__ char smem[];
    const uint32_t sb = smem_u32(smem);

    const int tid  = threadIdx.x;
    const int wid  = tid >> 5;
    const int lane = tid & 31;
    const int cN   = blockIdx.x;
    const int cM   = blockIdx.y;
    const int wm   = wid & 1;    // 0..1
    const int wn   = wid >> 1;   // 0..3

    // ---- cp.async geometry: 1 x 16B per thread per tile ----
    // 128 rows x 2 chunks = 256 items
    const int r0 = tid >> 1, c0 = tid & 1;
    const uint32_t so0 = sw_off(r0, c0);
    const size_t offA = (size_t)(cM * 128 + r0) * K + c0 * 8;
    const size_t offB = (size_t)(cN * 128 + r0) * K + c0 * 8;

#define LOAD_STAGE(s, k0)                                        \
    do {                                                          \
        CP16(sb + TILE_ST(s, 0) + so0, Ahi + offA + (k0));        \
        CP16(sb + TILE_ST(s, 1) + so0, Alo + offA + (k0));        \
        CP16(sb + TILE_ST(s, 2) + so0, Bhi + offB + (k0));        \
        CP16(sb + TILE_ST(s, 3) + so0, Blo + offB + (k0));        \
    } while (0)

    // per-warp ldmatrix base offsets
    const int arow = wm * 64 + (lane & 15);   // + mf*16
    const int brow = wn * 32 + (lane & 15);   // + bf*16
    const int chi  = lane >> 4;               // 16B column sub-chunk (0/1)

    uint32_t Ah[4][4], Al[4][4], Bh[2][4], Bl[2][4];

#define FRAG_LOAD(st)                                                        \
    do {                                                                      \
        _Pragma("unroll")                                                     \
        for (int mf = 0; mf < 4; mf++) {                                      \
            const uint32_t ao = sw_off(arow + mf * 16, chi);                  \
            LDSM_X4(Ah[mf], sb + TILE_ST(st, 0) + ao);                        \
            LDSM_X4(Al[mf], sb + TILE_ST(st, 1) + ao);                        \
        }                                                                     \
        _Pragma("unroll")                                                     \
        for (int bf = 0; bf < 2; bf++) {                                      \
            const uint32_t bo = sw_off(brow + bf * 16, chi);                  \
            LDSM_X4(Bh[bf], sb + TILE_ST(st, 2) + bo);                        \
            LDSM_X4(Bl[bf], sb + TILE_ST(st, 3) + bo);                        \
        }                                                                     \
    } while (0)

// term-major: 3 passes of 16 independent-accumulator MMAs each
#define MMA_ALL()                                                            \
    do {                                                                      \
        _Pragma("unroll")                                                     \
        for (int mf = 0; mf < 4; mf++) {                                      \
            _Pragma("unroll")                                                 \
            for (int nf = 0; nf < 4; nf++) {                                  \
                const int g = nf >> 1, h = nf & 1;                            \
                MMA_BF16(acc[mf][nf], Ah[mf], Bh[g][h], Bh[g][h + 2]);        \
            }                                                                 \
        }                                                                     \
        _Pragma("unroll")                                                     \
        for (int mf = 0; mf < 4; mf++) {                                      \
            _Pragma("unroll")                                                 \
            for (int nf = 0; nf < 4; nf++) {                                  \
                const int g = nf >> 1, h = nf & 1;                            \
                MMA_BF16(acc[mf][nf], Ah[mf], Bl[g][h], Bl[g][h + 2]);        \
            }                                                                 \
        }                                                                     \
        _Pragma("unroll")                                                     \
        for (int mf = 0; mf < 4; mf++) {                                      \
            _Pragma("unroll")                                                 \
            for (int nf = 0; nf < 4; nf++) {                                  \
                const int g = nf >> 1, h = nf & 1;                            \
                MMA_BF16(acc[mf][nf], Al[mf], Bh[g][h], Bh[g][h + 2]);        \
            }                                                                 \
        }                                                                     \
    } while (0)

    float acc[4][4][4];
#pragma unroll
    for (int i = 0; i < 4; i++)
#pragma unroll
        for (int j = 0; j < 4; j++)
#pragma unroll
            for (int r = 0; r < 4; r++) acc[i][j][r] = 0.0f;

    const int NC = K >> 4;   // 48 chunks of 16

    // ---- prologue: 3 stages in flight ----
    LOAD_STAGE(0, 0);   CP_COMMIT();
    LOAD_STAGE(1, 16);  CP_COMMIT();
    LOAD_STAGE(2, 32);  CP_COMMIT();
    CP_WAIT2();
    __syncthreads();

    for (int kc = 0; kc < NC; kc++) {
        const int cur = kc & 3;

        FRAG_LOAD(cur);
        // refill the slot freed last iteration: slot (kc+3)&3 == (kc-1)&3,
        // whose reads completed before the previous iteration's barrier.
        if (kc + 3 < NC) LOAD_STAGE((kc + 3) & 3, (kc + 3) * 16);
        CP_COMMIT();

        MMA_ALL();

        if (kc + 1 < NC) {
            CP_WAIT2();
            __syncthreads();
        }
    }

    // ---- epilogue: bias + fp32 store ----
#pragma unroll
    for (int mf = 0; mf < 4; mf++) {
        const int row = cM * 128 + wm * 64 + mf * 16 + (lane >> 2);
#pragma unroll
        for (int nf = 0; nf < 4; nf++) {
            const int col = cN * 128 + wn * 32 + nf * 8 + (lane & 3) * 2;
            const float2 bb = *reinterpret_cast<const float2*>(bias + col);
            float2 o0, o1;
            o0.x = acc[mf][nf][0] + bb.x;  o0.y = acc[mf][nf][1] + bb.y;
            o1.x = acc[mf][nf][2] + bb.x;  o1.y = acc[mf][nf][3] + bb.y;
            *reinterpret_cast<float2*>(Cout + (size_t)row * N + col) = o0;
            *reinterpret_cast<float2*>(Cout + (size_t)(row + 8) * N + col) = o1;
        }
    }
#undef LOAD_STAGE
#undef FRAG_LOAD
#undef MMA_ALL
}

// ---------------------------------------------------------------------------
// Attention: one CTA per (b, h); 4 q-rows per warp per iteration so the
// sk/sv smem loads amortize 4x (crossbar-bound kernel).
// Writes bf16 hi/lo split of output directly.
// ---------------------------------------------------------------------------
__global__ __launch_bounds__(256)
void attention_kernel(const float* __restrict__ qkv,
                      const float* __restrict__ mask,
                      __nv_bfloat16* __restrict__ ohi,
                      __nv_bfloat16* __restrict__ olo)
{
    __shared__ float sk[NTOK][HD + 1];
    __shared__ float sv[NTOK][HD + 1];
    __shared__ float sq[8][4][HD];
    __shared__ float sp[8][4][NTOK];

    const int bh = blockIdx.x;
    const int b  = bh / H_;
    const int h  = bh % H_;
    const int tid  = threadIdx.x;
    const int warp = tid >> 5;
    const int lane = tid & 31;

    const size_t base = (size_t)b * NTOK * K3C + (size_t)h * HD;
    for (int idx = tid; idx < NTOK * HD; idx += 256) {
        const int j = idx / HD, d = idx % HD;
        sk[j][d] = qkv[base + (size_t)j * K3C + C_ + d];
        sv[j][d] = qkv[base + (size_t)j * K3C + 2 * C_ + d];
    }
    __syncthreads();

    const float scale = 0.125f;
    const float* mrow_base = mask + (size_t)b * NTOK * NTOK;
    const int j0 = lane;
    const int j1 = lane + 32;
    const int j2 = (lane < 4) ? lane + 64 : 67;   // clamped; masked below

    // 17 groups of 4 rows
    for (int g = warp; g < 17; g += 8) {
        const int row0 = g * 4;

        // stage 4 scaled q rows
#pragma unroll
        for (int r = 0; r < 4; r++) {
            sq[warp][r][lane]      = qkv[base + (size_t)(row0 + r) * K3C + lane]      * scale;
            sq[warp][r][lane + 32] = qkv[base + (size_t)(row0 + r) * K3C + lane + 32] * scale;
        }
        __syncwarp();

        // scores: 4 rows x 3 key slots; sk loads shared across the 4 rows
        float s[4][3];
#pragma unroll
        for (int r = 0; r < 4; r++)
            s[r][0] = s[r][1] = s[r][2] = 0.0f;

#pragma unroll
        for (int d = 0; d < HD; d++) {
            const float k0 = sk[j0][d];
            const float k1 = sk[j1][d];
            const float k2 = sk[j2][d];
#pragma unroll
            for (int r = 0; r < 4; r++) {
                const float q = sq[warp][r][d];
                s[r][0] = fmaf(q, k0, s[r][0]);
                s[r][1] = fmaf(q, k1, s[r][1]);
                s[r][2] = fmaf(q, k2, s[r][2]);
            }
        }

        // add mask; invalidate clamped j2 lanes
#pragma unroll
        for (int r = 0; r < 4; r++) {
            const float* mrow = mrow_base + (size_t)(row0 + r) * NTOK;
            s[r][0] += mrow[j0];
            s[r][1] += mrow[j1];
            s[r][2] = (lane < 4) ? (s[r][2] + mrow[j2]) : -CUDART_INF_F;
        }

        // softmax per row
#pragma unroll
        for (int r = 0; r < 4; r++) {
            float mx = fmaxf(fmaxf(s[r][0], s[r][1]), s[r][2]);
#pragma unroll
            for (int off = 16; off > 0; off >>= 1)
                mx = fmaxf(mx, __shfl_xor_sync(0xffffffffu, mx, off));

            const float e0 = __expf(s[r][0] - mx);
            const float e1 = __expf(s[r][1] - mx);
            const float e2 = (lane < 4) ? __expf(s[r][2] - mx) : 0.0f;
            float sum = e0 + e1 + e2;
#pragma unroll
            for (int off = 16; off > 0; off >>= 1)
                sum += __shfl_xor_sync(0xffffffffu, sum, off);
            const float inv = 1.0f / sum;

            sp[warp][r][j0] = e0 * inv;
            sp[warp][r][j1] = e1 * inv;
            if (lane < 4) sp[warp][r][j2] = e2 * inv;
        }
        __syncwarp();

        // PV: sv loads shared across the 4 rows
        float o[4][2];
#pragma unroll
        for (int r = 0; r < 4; r++) o[r][0] = o[r][1] = 0.0f;

#pragma unroll
        for (int j = 0; j < NTOK; j++) {
            const float v0 = sv[j][lane];
            const float v1 = sv[j][lane + 32];
#pragma unroll
            for (int r = 0; r < 4; r++) {
                const float p = sp[warp][r][j];
                o[r][0] = fmaf(p, v0, o[r][0]);
                o[r][1] = fmaf(p, v1, o[r][1]);
            }
        }

#pragma unroll
        for (int r = 0; r < 4; r++) {
            const size_t obase = ((size_t)b * NTOK + row0 + r) * C_ + (size_t)h * HD;
            __nv_bfloat16 hh, ll;
            split2(o[r][0], hh, ll);
            ohi[obase + lane]      = hh;  olo[obase + lane]      = ll;
            split2(o[r][1], hh, ll);
            ohi[obase + lane + 32] = hh;  olo[obase + lane + 32] = ll;
        }
        __syncwarp();
    }
}

// ---------------------------------------------------------------------------
extern "C" void kernel_launch(void* const* d_in, const int* in_sizes, int n_in,
                              void* d_out, int out_size)
{
    const float* x      = (const float*)d_in[0];
    const float* pe     = (const float*)d_in[1];
    const float* mask   = (const float*)d_in[2];
    const float* w_qkv  = (const float*)d_in[3];
    const float* b_qkv  = (const float*)d_in[4];
    const float* w_proj = (const float*)d_in[5];
    const float* b_proj = (const float*)d_in[6];
    float* out = (float*)d_out;

    float*         qkv_buf; cudaGetSymbolAddress((void**)&qkv_buf, g_qkv);
    __nv_bfloat16 *xhi, *xlo, *whi, *wlo, *phi, *plo, *ahi, *alo;
    cudaGetSymbolAddress((void**)&xhi, g_xhi);
    cudaGetSymbolAddress((void**)&xlo, g_xlo);
    cudaGetSymbolAddress((void**)&whi, g_whi);
    cudaGetSymbolAddress((void**)&wlo, g_wlo);
    cudaGetSymbolAddress((void**)&phi, g_phi);
    cudaGetSymbolAddress((void**)&plo, g_plo);
    cudaGetSymbolAddress((void**)&ahi, g_ahi);
    cudaGetSymbolAddress((void**)&alo, g_alo);

    cudaFuncSetAttribute(gemm_bf16x3_kernel,
                         cudaFuncAttributeMaxDynamicSharedMemorySize, GEMM_SMEM);

    // 0) precompute bf16 splits
    {
        const size_t nx = (size_t)M_ * C_ / 4;
        split_x_pe_kernel<<<(unsigned)((nx + 255) / 256), 256>>>(x, pe, xhi, xlo);
        const size_t nw = (size_t)K3C * C_;
        split_w_kernel<<<(unsigned)((nw / 4 + 255) / 256), 256>>>(w_qkv, whi, wlo, nw);
        const size_t np = (size_t)C_ * C_;
        split_w_kernel<<<(unsigned)((np / 4 + 255) / 256), 256>>>(w_proj, phi, plo, np);
    }

    // 1) QKV projection: (M x 768) @ (768 x 2304)^T + bias -> g_qkv (fp32)
    {
        dim3 grid(K3C / 128, M_ / 128);
        gemm_bf16x3_kernel<<<grid, 256, GEMM_SMEM>>>(xhi, xlo, whi, wlo,
                                                     b_qkv, qkv_buf, K3C, C_);
    }

    // 2) Attention -> bf16 split output
    attention_kernel<<<B_ * H_, 256>>>(qkv_buf, mask, ahi, alo);

    // 3) Output projection -> d_out
    {
        dim3 grid(C_ / 128, M_ / 128);
        gemm_bf16x3_kernel<<<grid, 256, GEMM_SMEM>>>(ahi, alo, phi, plo,
                                                     b_proj, out, C_, C_);
    }
}